// round 4
// baseline (speedup 1.0000x reference)
#include <cuda_runtime.h>
#include <cuda_bf16.h>
#include <cstdint>
#include <math.h>

#define BATCH 8192
#define UNITS 1024
#define KTOT  2048
#define NCOL  4096

// ---------------- device scratch (allocation-free rule) ----------------
__device__ __nv_bfloat16 gA_hi[(size_t)BATCH * KTOT];
__device__ __nv_bfloat16 gA_lo[(size_t)BATCH * KTOT];
__device__ __nv_bfloat16 gB_hi[(size_t)NCOL * KTOT];   // [n][k] K-major (transposed)
__device__ __nv_bfloat16 gB_lo[(size_t)NCOL * KTOT];

// ---------------- helpers ----------------
__device__ __forceinline__ uint32_t smem_to_u32(const void* p) {
    uint32_t a;
    asm("{ .reg .u64 t; cvta.to.shared.u64 t, %1; cvt.u32.u64 %0, t; }" : "=r"(a) : "l"(p));
    return a;
}
__device__ __forceinline__ void cp16(uint32_t dst, const void* src) {
    asm volatile("cp.async.cg.shared.global [%0], [%1], 16;" :: "r"(dst), "l"(src));
}
#define CP_COMMIT() asm volatile("cp.async.commit_group;" ::: "memory")

#define LDSM4(r, addr) \
    asm volatile("ldmatrix.sync.aligned.m8n8.x4.shared.b16 {%0,%1,%2,%3}, [%4];" \
        : "=r"((r)[0]), "=r"((r)[1]), "=r"((r)[2]), "=r"((r)[3]) : "r"(addr))

__device__ __forceinline__ void mma_bf16(float* c, const uint32_t* a, uint32_t b0, uint32_t b1) {
    asm volatile("mma.sync.aligned.m16n8k16.row.col.f32.bf16.bf16.f32 "
        "{%0,%1,%2,%3}, {%4,%5,%6,%7}, {%8,%9}, {%0,%1,%2,%3};"
        : "+f"(c[0]), "+f"(c[1]), "+f"(c[2]), "+f"(c[3])
        : "r"(a[0]), "r"(a[1]), "r"(a[2]), "r"(a[3]), "r"(b0), "r"(b1));
}

__device__ __forceinline__ float sigf(float v) { return 1.0f / (1.0f + expf(-v)); }

// ---------------- conversion kernels ----------------
__global__ __launch_bounds__(256)
void convA_kernel(const float4* __restrict__ x4, const float4* __restrict__ h4)
{
    size_t idx4 = (size_t)blockIdx.x * 256 + threadIdx.x;   // 0 .. 8192*512-1
    int m  = (int)(idx4 >> 9);
    int c4 = (int)(idx4 & 511);
    float4 v = (c4 < 256) ? x4[(size_t)m * 256 + c4]
                          : h4[(size_t)m * 256 + (c4 - 256)];
    __nv_bfloat16 hx = __float2bfloat16_rn(v.x);
    __nv_bfloat16 hy = __float2bfloat16_rn(v.y);
    __nv_bfloat16 hz = __float2bfloat16_rn(v.z);
    __nv_bfloat16 hw = __float2bfloat16_rn(v.w);
    __nv_bfloat162 ph0; ph0.x = hx; ph0.y = hy;
    __nv_bfloat162 ph1; ph1.x = hz; ph1.y = hw;
    ((__nv_bfloat162*)gA_hi)[idx4 * 2]     = ph0;
    ((__nv_bfloat162*)gA_hi)[idx4 * 2 + 1] = ph1;
    __nv_bfloat162 pl0, pl1;
    pl0.x = __float2bfloat16_rn(v.x - __bfloat162float(hx));
    pl0.y = __float2bfloat16_rn(v.y - __bfloat162float(hy));
    pl1.x = __float2bfloat16_rn(v.z - __bfloat162float(hz));
    pl1.y = __float2bfloat16_rn(v.w - __bfloat162float(hw));
    ((__nv_bfloat162*)gA_lo)[idx4 * 2]     = pl0;
    ((__nv_bfloat162*)gA_lo)[idx4 * 2 + 1] = pl1;
}

__global__ __launch_bounds__(256)
void convB_kernel(const float* __restrict__ W, const float* __restrict__ U)
{
    __shared__ float tile[32][33];
    const int n0 = blockIdx.x * 32, k0 = blockIdx.y * 32;
    #pragma unroll
    for (int i = 0; i < 4; i++) {
        int k = k0 + threadIdx.y + i * 8;
        int n = n0 + threadIdx.x;
        float v = (k < 1024) ? W[(size_t)k * 4096 + n] : U[(size_t)(k - 1024) * 4096 + n];
        tile[threadIdx.y + i * 8][threadIdx.x] = v;
    }
    __syncthreads();
    #pragma unroll
    for (int i = 0; i < 4; i++) {
        int nn = threadIdx.y + i * 8;   // n within tile
        int kk = threadIdx.x;           // k within tile
        float v = tile[kk][nn];
        __nv_bfloat16 hi = __float2bfloat16_rn(v);
        __nv_bfloat16 lo = __float2bfloat16_rn(v - __bfloat162float(hi));
        gB_hi[(size_t)(n0 + nn) * KTOT + k0 + kk] = hi;
        gB_lo[(size_t)(n0 + nn) * KTOT + k0 + kk] = lo;
    }
}

// ---------------- fused MMA + LSTM-gate kernel ----------------
// CTA tile: 128 (M) x 256 (N) x BK=32. N cols interleaved: col = 4*u_local + gate (64 units/CTA).
// 512 threads = 16 warps: warp_m = warp&3 (32 M-rows), warp_n = warp>>2 (64 N-cols).
// 3-stage cp.async pipeline, one __syncthreads per iteration.
#define PADB 80
#define A_TILE_B (128 * PADB)         // 10240
#define B_TILE_B (256 * PADB)         // 20480
#define OFF_AHI 0
#define OFF_ALO A_TILE_B
#define OFF_BHI (2 * A_TILE_B)
#define OFF_BLO (2 * A_TILE_B + B_TILE_B)
#define STAGE_B (2 * A_TILE_B + 2 * B_TILE_B)   // 61440
#define NSTAGE 3
#define SMEM_TOTAL (NSTAGE * STAGE_B)           // 184320
#define NITER 64                                // 2048 / 32
#define ZS4 65                                  // z row stride in float4s (260 floats)

__global__ __launch_bounds__(512, 1)
void lstm_mma_kernel(const float* __restrict__ c_prev,
                     const float* __restrict__ bias,
                     const float* __restrict__ pf,
                     const float* __restrict__ pi,
                     const float* __restrict__ po,
                     float* __restrict__ out)
{
    extern __shared__ char smc[];
    const uint32_t sb = smem_to_u32(smc);
    const int tid  = threadIdx.x;
    const int lane = tid & 31;
    const int warp = tid >> 5;
    const int warp_m = warp & 3;        // 4 warps over M (32 rows each)
    const int warp_n = warp >> 2;       // 4 warps over N (64 cols each)
    const int bm = blockIdx.y * 128;
    const int u0 = blockIdx.x * 64;     // 64 units per CTA

    // ---- per-thread load slots ----
    // A: row = tid>>2 (0..127), chunk = tid&3  -> hi + lo       (2 cp16)
    // B: rows tid>>2 and (tid>>2)+128, chunk = tid&3 -> hi + lo (4 cp16)
    const int lr = tid >> 2, cch = tid & 3;
    const uint32_t sA = (uint32_t)(lr * PADB + cch * 16);
    const uint32_t gA = (uint32_t)(((size_t)(bm + lr) * KTOT + cch * 8) * 2);
    uint32_t sB[2], gB[2];
    #pragma unroll
    for (int p = 0; p < 2; p++) {
        const int r = lr + p * 128;
        sB[p] = (uint32_t)(r * PADB + cch * 16);
        const int ng = (r & 3) * 1024 + u0 + (r >> 2);   // gate-interleaved B row
        gB[p] = (uint32_t)(((size_t)ng * KTOT + cch * 8) * 2);
    }
    const char* pAh = (const char*)gA_hi;
    const char* pAl = (const char*)gA_lo;
    const char* pBh = (const char*)gB_hi;
    const char* pBl = (const char*)gB_lo;

    // prologue: stages 0,1 hold k-chunks 0,1
    #pragma unroll
    for (int i = 0; i < 2; i++) {
        const uint32_t st = sb + i * STAGE_B;
        const uint32_t kb = (uint32_t)(i * 64);
        cp16(st + OFF_AHI + sA, pAh + gA + kb);
        cp16(st + OFF_ALO + sA, pAl + gA + kb);
        #pragma unroll
        for (int p = 0; p < 2; p++) {
            cp16(st + OFF_BHI + sB[p], pBh + gB[p] + kb);
            cp16(st + OFF_BLO + sB[p], pBl + gB[p] + kb);
        }
        CP_COMMIT();
    }

    float acc[2][8][4];
    #pragma unroll
    for (int mt = 0; mt < 2; mt++)
        #pragma unroll
        for (int nt = 0; nt < 8; nt++)
            #pragma unroll
            for (int q = 0; q < 4; q++) acc[mt][nt][q] = 0.0f;

    // ldmatrix address components (fixed per thread)
    const int a_row = warp_m * 32 + (lane & 15);                         // + mt*16
    const int a_kc  = (lane >> 4);                                       // + ks*2
    const int b_row = warp_n * 64 + (lane & 7) + ((lane >> 4) & 1) * 8;  // + nt2*16
    const int b_kc  = ((lane >> 3) & 1);                                 // + ks*2

    int stage = 0;
    for (int i = 0; i < NITER; i++) {
        if (i < NITER - 1) asm volatile("cp.async.wait_group 1;" ::: "memory");
        else               asm volatile("cp.async.wait_group 0;" ::: "memory");
        __syncthreads();

        // issue loads for chunk i+2 into the stage consumed at iter i-1
        if (i + 2 < NITER) {
            int ls = stage - 1; if (ls < 0) ls += NSTAGE;
            const uint32_t stn = sb + (uint32_t)ls * STAGE_B;
            const uint32_t kb  = (uint32_t)((i + 2) * 64);
            cp16(stn + OFF_AHI + sA, pAh + gA + kb);
            cp16(stn + OFF_ALO + sA, pAl + gA + kb);
            #pragma unroll
            for (int p = 0; p < 2; p++) {
                cp16(stn + OFF_BHI + sB[p], pBh + gB[p] + kb);
                cp16(stn + OFF_BLO + sB[p], pBl + gB[p] + kb);
            }
            CP_COMMIT();
        }

        const uint32_t st = sb + (uint32_t)stage * STAGE_B;
        #pragma unroll
        for (int ks = 0; ks < 2; ks++) {
            uint32_t ah[2][4], al[2][4], bh[4][4], bl[4][4];
            #pragma unroll
            for (int mt = 0; mt < 2; mt++)
                LDSM4(ah[mt], st + OFF_AHI + (uint32_t)((a_row + mt * 16) * PADB + (a_kc + ks * 2) * 16));
            #pragma unroll
            for (int nt2 = 0; nt2 < 4; nt2++)
                LDSM4(bh[nt2], st + OFF_BHI + (uint32_t)((b_row + nt2 * 16) * PADB + (b_kc + ks * 2) * 16));
            // hi x hi
            #pragma unroll
            for (int mt = 0; mt < 2; mt++)
                #pragma unroll
                for (int nt = 0; nt < 8; nt++)
                    mma_bf16(acc[mt][nt], ah[mt], bh[nt >> 1][(nt & 1) * 2], bh[nt >> 1][(nt & 1) * 2 + 1]);
            // lo x hi
            #pragma unroll
            for (int mt = 0; mt < 2; mt++)
                LDSM4(al[mt], st + OFF_ALO + (uint32_t)((a_row + mt * 16) * PADB + (a_kc + ks * 2) * 16));
            #pragma unroll
            for (int mt = 0; mt < 2; mt++)
                #pragma unroll
                for (int nt = 0; nt < 8; nt++)
                    mma_bf16(acc[mt][nt], al[mt], bh[nt >> 1][(nt & 1) * 2], bh[nt >> 1][(nt & 1) * 2 + 1]);
            // hi x lo
            #pragma unroll
            for (int nt2 = 0; nt2 < 4; nt2++)
                LDSM4(bl[nt2], st + OFF_BLO + (uint32_t)((b_row + nt2 * 16) * PADB + (b_kc + ks * 2) * 16));
            #pragma unroll
            for (int mt = 0; mt < 2; mt++)
                #pragma unroll
                for (int nt = 0; nt < 8; nt++)
                    mma_bf16(acc[mt][nt], ah[mt], bl[nt >> 1][(nt & 1) * 2], bl[nt >> 1][(nt & 1) * 2 + 1]);
        }

        if (++stage == NSTAGE) stage = 0;
    }

    // ---- epilogue: stage z tile (128 x 256) to smem, then fused LSTM gates ----
    __syncthreads();   // all warps done reading pipeline stages before aliasing as z
    float* z = (float*)smc;   // stride 260 floats (65 float4s) -> 133120 B
    #pragma unroll
    for (int mt = 0; mt < 2; mt++) {
        const int row = warp_m * 32 + mt * 16 + (lane >> 2);
        #pragma unroll
        for (int nt = 0; nt < 8; nt++) {
            const int col = warp_n * 64 + nt * 8 + (lane & 3) * 2;
            z[row * (ZS4 * 4) + col]           = acc[mt][nt][0];
            z[row * (ZS4 * 4) + col + 1]       = acc[mt][nt][1];
            z[(row + 8) * (ZS4 * 4) + col]     = acc[mt][nt][2];
            z[(row + 8) * (ZS4 * 4) + col + 1] = acc[mt][nt][3];
        }
    }
    __syncthreads();

    const float4* zv4 = (const float4*)smc;
    #pragma unroll
    for (int pass = 0; pass < 16; pass++) {
        const int idx = pass * 512 + tid;     // 0 .. 8191
        const int m = idx >> 6;               // 0..127
        const int u = idx & 63;               // 0..63
        const int mg = bm + m;
        const int ug = u0 + u;
        const float4 zz = zv4[m * ZS4 + u];   // (zf, zi, zc, zo)
        const float zf = zz.x + bias[ug];
        const float zi = zz.y + bias[1024 + ug];
        const float zc = zz.z + bias[2048 + ug];
        const float zo = zz.w + bias[3072 + ug];
        const float cp = c_prev[(size_t)mg * UNITS + ug];
        const float f  = sigf(zf + pf[ug] * cp);
        const float ig = sigf(zi + pi[ug] * cp);
        const float ct = tanhf(zc);
        const float c  = f * cp + ig * ct;
        const float o  = sigf(zo + po[ug] * c);
        out[(size_t)mg * UNITS + ug] = o * tanhf(c);
        out[(size_t)BATCH * UNITS + (size_t)mg * UNITS + ug] = c;
    }
}

// ---------------- launch ----------------
extern "C" void kernel_launch(void* const* d_in, const int* in_sizes, int n_in,
                              void* d_out, int out_size)
{
    const float* x      = (const float*)d_in[0];
    const float* c_prev = (const float*)d_in[1];
    const float* h_prev = (const float*)d_in[2];
    const float* W      = (const float*)d_in[3];
    const float* U      = (const float*)d_in[4];
    const float* bias   = (const float*)d_in[5];
    const float* pf     = (const float*)d_in[6];
    const float* pi     = (const float*)d_in[7];
    const float* po     = (const float*)d_in[8];
    float* out = (float*)d_out;

    convA_kernel<<<(BATCH * KTOT / 4) / 256, 256>>>((const float4*)x, (const float4*)h_prev);
    convB_kernel<<<dim3(NCOL / 32, KTOT / 32), dim3(32, 8)>>>(W, U);

    cudaFuncSetAttribute(lstm_mma_kernel,
                         cudaFuncAttributeMaxDynamicSharedMemorySize, SMEM_TOTAL);
    lstm_mma_kernel<<<dim3(UNITS / 64, BATCH / 128), 512, SMEM_TOTAL>>>(
        c_prev, bias, pf, pi, po, out);
}

// round 5
// speedup vs baseline: 1.2440x; 1.2440x over previous
#include <cuda_runtime.h>
#include <cuda_bf16.h>
#include <cstdint>
#include <math.h>

#define BATCH 8192
#define UNITS 1024
#define KTOT  2048
#define NCOL  4096

// ---------------- device scratch (allocation-free rule) ----------------
__device__ __nv_bfloat16 gA_hi[(size_t)BATCH * KTOT];
__device__ __nv_bfloat16 gA_lo[(size_t)BATCH * KTOT];
__device__ __nv_bfloat16 gB_hi[(size_t)NCOL * KTOT];   // [n][k] K-major (transposed)
__device__ __nv_bfloat16 gB_lo[(size_t)NCOL * KTOT];

// ---------------- helpers ----------------
__device__ __forceinline__ uint32_t smem_to_u32(const void* p) {
    uint32_t a;
    asm("{ .reg .u64 t; cvta.to.shared.u64 t, %1; cvt.u32.u64 %0, t; }" : "=r"(a) : "l"(p));
    return a;
}
__device__ __forceinline__ void cp16(uint32_t dst, const void* src) {
    asm volatile("cp.async.cg.shared.global [%0], [%1], 16;" :: "r"(dst), "l"(src));
}
#define CP_COMMIT() asm volatile("cp.async.commit_group;" ::: "memory")

#define LDSM4(r, addr) \
    asm volatile("ldmatrix.sync.aligned.m8n8.x4.shared.b16 {%0,%1,%2,%3}, [%4];" \
        : "=r"((r)[0]), "=r"((r)[1]), "=r"((r)[2]), "=r"((r)[3]) : "r"(addr))

__device__ __forceinline__ void mma_bf16(float* c, const uint32_t* a, uint32_t b0, uint32_t b1) {
    asm volatile("mma.sync.aligned.m16n8k16.row.col.f32.bf16.bf16.f32 "
        "{%0,%1,%2,%3}, {%4,%5,%6,%7}, {%8,%9}, {%0,%1,%2,%3};"
        : "+f"(c[0]), "+f"(c[1]), "+f"(c[2]), "+f"(c[3])
        : "r"(a[0]), "r"(a[1]), "r"(a[2]), "r"(a[3]), "r"(b0), "r"(b1));
}

__device__ __forceinline__ float sigf(float v) { return 1.0f / (1.0f + expf(-v)); }

// ---------------- conversion kernels ----------------
__global__ __launch_bounds__(256)
void convA_kernel(const float4* __restrict__ x4, const float4* __restrict__ h4)
{
    size_t idx4 = (size_t)blockIdx.x * 256 + threadIdx.x;   // 0 .. 8192*512-1
    int m  = (int)(idx4 >> 9);
    int c4 = (int)(idx4 & 511);
    float4 v = (c4 < 256) ? x4[(size_t)m * 256 + c4]
                          : h4[(size_t)m * 256 + (c4 - 256)];
    __nv_bfloat16 hx = __float2bfloat16_rn(v.x);
    __nv_bfloat16 hy = __float2bfloat16_rn(v.y);
    __nv_bfloat16 hz = __float2bfloat16_rn(v.z);
    __nv_bfloat16 hw = __float2bfloat16_rn(v.w);
    __nv_bfloat162 ph0; ph0.x = hx; ph0.y = hy;
    __nv_bfloat162 ph1; ph1.x = hz; ph1.y = hw;
    ((__nv_bfloat162*)gA_hi)[idx4 * 2]     = ph0;
    ((__nv_bfloat162*)gA_hi)[idx4 * 2 + 1] = ph1;
    __nv_bfloat162 pl0, pl1;
    pl0.x = __float2bfloat16_rn(v.x - __bfloat162float(hx));
    pl0.y = __float2bfloat16_rn(v.y - __bfloat162float(hy));
    pl1.x = __float2bfloat16_rn(v.z - __bfloat162float(hz));
    pl1.y = __float2bfloat16_rn(v.w - __bfloat162float(hw));
    ((__nv_bfloat162*)gA_lo)[idx4 * 2]     = pl0;
    ((__nv_bfloat162*)gA_lo)[idx4 * 2 + 1] = pl1;
}

__global__ __launch_bounds__(256)
void convB_kernel(const float* __restrict__ W, const float* __restrict__ U)
{
    __shared__ float tile[32][33];
    const int n0 = blockIdx.x * 32, k0 = blockIdx.y * 32;
    #pragma unroll
    for (int i = 0; i < 4; i++) {
        int k = k0 + threadIdx.y + i * 8;
        int n = n0 + threadIdx.x;
        float v = (k < 1024) ? W[(size_t)k * 4096 + n] : U[(size_t)(k - 1024) * 4096 + n];
        tile[threadIdx.y + i * 8][threadIdx.x] = v;
    }
    __syncthreads();
    #pragma unroll
    for (int i = 0; i < 4; i++) {
        int nn = threadIdx.y + i * 8;   // n within tile
        int kk = threadIdx.x;           // k within tile
        float v = tile[kk][nn];
        __nv_bfloat16 hi = __float2bfloat16_rn(v);
        __nv_bfloat16 lo = __float2bfloat16_rn(v - __bfloat162float(hi));
        gB_hi[(size_t)(n0 + nn) * KTOT + k0 + kk] = hi;
        gB_lo[(size_t)(n0 + nn) * KTOT + k0 + kk] = lo;
    }
}

// ---------------- fused MMA + LSTM-gate kernel ----------------
// CTA tile: 128 (M) x 128 (N) x BK=32. N cols interleaved: col = 4*u_local + gate (32 units/CTA).
// 256 threads = 8 warps: warp_m = warp&3 (32 M-rows), warp_n = warp>>2 (64 N-cols).
// 3-stage cp.async pipeline, swizzled 64B rows, ONE __syncthreads per iteration.
// Swizzle: 16B-chunk c at row r stored at chunk (c ^ ((r>>1)&3)). Conflict-free ldmatrix.
#define TILE_B 8192                 // 128 rows * 64 B
#define OFF_AHI 0
#define OFF_ALO 8192
#define OFF_BHI 16384
#define OFF_BLO 24576
#define STAGE_B 32768
#define NSTAGE 3
#define SMEM_TOTAL (NSTAGE * STAGE_B)   // 98304
#define NITER 64                        // 2048 / 32
#define ZS4 33                          // z row stride in float4s (132 floats)

__global__ __launch_bounds__(256, 2)
void lstm_mma_kernel(const float* __restrict__ c_prev,
                     const float* __restrict__ bias,
                     const float* __restrict__ pf,
                     const float* __restrict__ pi,
                     const float* __restrict__ po,
                     float* __restrict__ out)
{
    extern __shared__ char smc[];
    const uint32_t sb = smem_to_u32(smc);
    const int tid  = threadIdx.x;
    const int lane = tid & 31;
    const int warp = tid >> 5;
    const int warp_m = warp & 3;        // 4 warps over M (32 rows each)
    const int warp_n = warp >> 2;       // 2 warps over N (64 cols each)
    const int bm = blockIdx.y * 128;
    const int u0 = blockIdx.x * 32;     // 32 units per CTA

    // ---- per-thread load slots (2 per tile): row = tid>>2 (+64), chunk = tid&3 ----
    const int lr = tid >> 2, cch = tid & 3;
    uint32_t soff[2], aoff[2], boff[2];
    #pragma unroll
    for (int p = 0; p < 2; p++) {
        const int r = lr + p * 64;
        soff[p] = (uint32_t)(r * 64 + ((cch ^ ((r >> 1) & 3)) << 4));
        aoff[p] = (uint32_t)(((size_t)(bm + r) * KTOT + cch * 8) * 2);
        const int ng = (r & 3) * 1024 + u0 + (r >> 2);   // gate-interleaved B row
        boff[p] = (uint32_t)(((size_t)ng * KTOT + cch * 8) * 2);
    }
    const char* pAh = (const char*)gA_hi;
    const char* pAl = (const char*)gA_lo;
    const char* pBh = (const char*)gB_hi;
    const char* pBl = (const char*)gB_lo;

    // prologue: stages 0,1 hold k-chunks 0,1
    #pragma unroll
    for (int i = 0; i < 2; i++) {
        const uint32_t st = sb + i * STAGE_B;
        const uint32_t kb = (uint32_t)(i * 64);
        #pragma unroll
        for (int p = 0; p < 2; p++) {
            cp16(st + OFF_AHI + soff[p], pAh + aoff[p] + kb);
            cp16(st + OFF_ALO + soff[p], pAl + aoff[p] + kb);
            cp16(st + OFF_BHI + soff[p], pBh + boff[p] + kb);
            cp16(st + OFF_BLO + soff[p], pBl + boff[p] + kb);
        }
        CP_COMMIT();
    }

    float acc[2][8][4];
    #pragma unroll
    for (int mt = 0; mt < 2; mt++)
        #pragma unroll
        for (int nt = 0; nt < 8; nt++)
            #pragma unroll
            for (int q = 0; q < 4; q++) acc[mt][nt][q] = 0.0f;

    // ldmatrix address components (fixed per thread, swizzle folded in)
    const int a_row = warp_m * 32 + (lane & 15);                         // + mt*16
    const int a_kc  = (lane >> 4);                                       // chunk += ks*2 (xor trick)
    const int b_row = warp_n * 64 + (lane & 7) + ((lane >> 4) & 1) * 8;  // + nt2*16
    const int b_kc  = ((lane >> 3) & 1);
    const uint32_t aob = (uint32_t)(a_row * 64 + ((a_kc ^ ((a_row >> 1) & 3)) << 4));
    const uint32_t bob = (uint32_t)(b_row * 64 + ((b_kc ^ ((b_row >> 1) & 3)) << 4));

    int stage = 0;
    for (int i = 0; i < NITER; i++) {
        if (i < NITER - 1) asm volatile("cp.async.wait_group 1;" ::: "memory");
        else               asm volatile("cp.async.wait_group 0;" ::: "memory");
        __syncthreads();   // single barrier: orders iter i-1 reads before stage reuse below

        // issue loads for chunk i+2 into stage (i+2)%3 (last read at iter i-1)
        if (i + 2 < NITER) {
            int ls = stage + 2; if (ls >= NSTAGE) ls -= NSTAGE;
            const uint32_t stn = sb + (uint32_t)ls * STAGE_B;
            const uint32_t kb  = (uint32_t)((i + 2) * 64);
            #pragma unroll
            for (int p = 0; p < 2; p++) {
                cp16(stn + OFF_AHI + soff[p], pAh + aoff[p] + kb);
                cp16(stn + OFF_ALO + soff[p], pAl + aoff[p] + kb);
                cp16(stn + OFF_BHI + soff[p], pBh + boff[p] + kb);
                cp16(stn + OFF_BLO + soff[p], pBl + boff[p] + kb);
            }
            CP_COMMIT();
        }

        const uint32_t st = sb + (uint32_t)stage * STAGE_B;
        #pragma unroll
        for (int ks = 0; ks < 2; ks++) {
            const uint32_t kx = (uint32_t)(ks << 5);   // xor 32 bytes selects chunk+2
            uint32_t ah[2][4], al[2][4], bh[4][4], bl[4][4];
            #pragma unroll
            for (int mt = 0; mt < 2; mt++)
                LDSM4(ah[mt], st + OFF_AHI + ((aob ^ kx) + mt * 1024));
            #pragma unroll
            for (int nt2 = 0; nt2 < 4; nt2++)
                LDSM4(bh[nt2], st + OFF_BHI + ((bob ^ kx) + nt2 * 1024));
            // hi x hi
            #pragma unroll
            for (int mt = 0; mt < 2; mt++)
                #pragma unroll
                for (int nt = 0; nt < 8; nt++)
                    mma_bf16(acc[mt][nt], ah[mt], bh[nt >> 1][(nt & 1) * 2], bh[nt >> 1][(nt & 1) * 2 + 1]);
            // lo x hi
            #pragma unroll
            for (int mt = 0; mt < 2; mt++)
                LDSM4(al[mt], st + OFF_ALO + ((aob ^ kx) + mt * 1024));
            #pragma unroll
            for (int mt = 0; mt < 2; mt++)
                #pragma unroll
                for (int nt = 0; nt < 8; nt++)
                    mma_bf16(acc[mt][nt], al[mt], bh[nt >> 1][(nt & 1) * 2], bh[nt >> 1][(nt & 1) * 2 + 1]);
            // hi x lo
            #pragma unroll
            for (int nt2 = 0; nt2 < 4; nt2++)
                LDSM4(bl[nt2], st + OFF_BLO + ((bob ^ kx) + nt2 * 1024));
            #pragma unroll
            for (int mt = 0; mt < 2; mt++)
                #pragma unroll
                for (int nt = 0; nt < 8; nt++)
                    mma_bf16(acc[mt][nt], ah[mt], bl[nt >> 1][(nt & 1) * 2], bl[nt >> 1][(nt & 1) * 2 + 1]);
        }

        if (++stage == NSTAGE) stage = 0;
    }

    // ---- epilogue: stage z tile (128 x 128) to smem, then fused LSTM gates ----
    __syncthreads();
    float* z = (float*)smc;   // stride 132 floats -> 67584 B (fits in 98304)
    #pragma unroll
    for (int mt = 0; mt < 2; mt++) {
        const int row = warp_m * 32 + mt * 16 + (lane >> 2);
        #pragma unroll
        for (int nt = 0; nt < 8; nt++) {
            const int col = warp_n * 64 + nt * 8 + (lane & 3) * 2;
            z[row * (ZS4 * 4) + col]           = acc[mt][nt][0];
            z[row * (ZS4 * 4) + col + 1]       = acc[mt][nt][1];
            z[(row + 8) * (ZS4 * 4) + col]     = acc[mt][nt][2];
            z[(row + 8) * (ZS4 * 4) + col + 1] = acc[mt][nt][3];
        }
    }
    __syncthreads();

    const float4* zv4 = (const float4*)smc;
    #pragma unroll
    for (int pass = 0; pass < 16; pass++) {
        const int idx = pass * 256 + tid;     // 0 .. 4095
        const int m = idx >> 5;               // 0..127
        const int u = idx & 31;               // 0..31
        const int mg = bm + m;
        const int ug = u0 + u;
        const float4 zz = zv4[m * ZS4 + u];   // (zf, zi, zc, zo)
        const float zf = zz.x + bias[ug];
        const float zi = zz.y + bias[1024 + ug];
        const float zc = zz.z + bias[2048 + ug];
        const float zo = zz.w + bias[3072 + ug];
        const float cp = c_prev[(size_t)mg * UNITS + ug];
        const float f  = sigf(zf + pf[ug] * cp);
        const float ig = sigf(zi + pi[ug] * cp);
        const float ct = tanhf(zc);
        const float c  = f * cp + ig * ct;
        const float o  = sigf(zo + po[ug] * c);
        out[(size_t)mg * UNITS + ug] = o * tanhf(c);
        out[(size_t)BATCH * UNITS + (size_t)mg * UNITS + ug] = c;
    }
}

// ---------------- launch ----------------
extern "C" void kernel_launch(void* const* d_in, const int* in_sizes, int n_in,
                              void* d_out, int out_size)
{
    const float* x      = (const float*)d_in[0];
    const float* c_prev = (const float*)d_in[1];
    const float* h_prev = (const float*)d_in[2];
    const float* W      = (const float*)d_in[3];
    const float* U      = (const float*)d_in[4];
    const float* bias   = (const float*)d_in[5];
    const float* pf     = (const float*)d_in[6];
    const float* pi     = (const float*)d_in[7];
    const float* po     = (const float*)d_in[8];
    float* out = (float*)d_out;

    convA_kernel<<<(BATCH * KTOT / 4) / 256, 256>>>((const float4*)x, (const float4*)h_prev);
    convB_kernel<<<dim3(NCOL / 32, KTOT / 32), dim3(32, 8)>>>(W, U);

    cudaFuncSetAttribute(lstm_mma_kernel,
                         cudaFuncAttributeMaxDynamicSharedMemorySize, SMEM_TOTAL);
    lstm_mma_kernel<<<dim3(UNITS / 32, BATCH / 128), 256, SMEM_TOTAL>>>(
        c_prev, bias, pf, pi, po, out);
}